// round 3
// baseline (speedup 1.0000x reference)
#include <cuda_runtime.h>

#define NN 50000
#define EE 800000
#define EMBD 64
#define LL 4
#define BN_EPS 1e-5f

// ---------------- scratch (device globals; no allocation allowed) ----------
__device__ __align__(256) float g_bufA[NN * EMBD];   // agg output / t2
__device__ __align__(256) float g_bufB[NN * EMBD];   // t (gemm1 out)
__device__ int   g_off[NN + 1];
__device__ int   g_cur[NN];
__device__ int   g_srcA[EE];
__device__ float g_wA[EE];
__device__ float g_sum[EMBD];
__device__ float g_sq[EMBD];
__device__ float g_scale[EMBD];
__device__ float g_shift[EMBD];

// ---------------- CSR build ------------------------------------------------
__global__ void k_init() {
    int i = blockIdx.x * blockDim.x + threadIdx.x;
    if (i < NN) g_cur[i] = 0;
    if (i < EMBD) { g_sum[i] = 0.f; g_sq[i] = 0.f; }
}

__global__ void k_hist(const int* __restrict__ ei) {
    int e = blockIdx.x * blockDim.x + threadIdx.x;
    if (e < EE) atomicAdd(&g_cur[ei[EE + e]], 1);
}

// single-block exclusive scan over g_cur -> g_off, g_cur(=cursor)
__global__ void k_scan() {
    __shared__ int s_warp[32];
    __shared__ int s_base;
    int tid = threadIdx.x, lane = tid & 31, wid = tid >> 5;
    if (tid == 0) s_base = 0;
    __syncthreads();
    for (int start = 0; start < NN; start += 1024) {
        int i = start + tid;
        int d = (i < NN) ? g_cur[i] : 0;
        int v = d;
        #pragma unroll
        for (int o = 1; o < 32; o <<= 1) {
            int t = __shfl_up_sync(0xffffffffu, v, o);
            if (lane >= o) v += t;
        }
        if (lane == 31) s_warp[wid] = v;
        __syncthreads();
        if (wid == 0) {
            int w = s_warp[lane];
            #pragma unroll
            for (int o = 1; o < 32; o <<= 1) {
                int t = __shfl_up_sync(0xffffffffu, w, o);
                if (lane >= o) w += t;
            }
            s_warp[lane] = w;
        }
        __syncthreads();
        int excl = s_base + (wid ? s_warp[wid - 1] : 0) + v - d;
        if (i < NN) { g_off[i] = excl; g_cur[i] = excl; }
        int tot = s_warp[31];
        __syncthreads();
        if (tid == 0) s_base += tot;
        __syncthreads();
    }
    if (threadIdx.x == 0) g_off[NN] = s_base;
}

__global__ void k_fill(const int* __restrict__ ei, const float* __restrict__ ew) {
    int e = blockIdx.x * blockDim.x + threadIdx.x;
    if (e < EE) {
        int d = ei[EE + e];
        int p = atomicAdd(&g_cur[d], 1);
        g_srcA[p] = ei[e];
        g_wA[p]   = ew[e];
    }
}

// ---------------- aggregation: warp per node, no atomics -------------------
// out = g_bufA
__global__ void k_agg(const float* __restrict__ h) {
    int gw   = (blockIdx.x * blockDim.x + threadIdx.x) >> 5;
    int lane = threadIdx.x & 31;
    if (gw >= NN) return;
    int beg = g_off[gw], end = g_off[gw + 1];
    const float2* h2 = (const float2*)h;
    float2 acc = h2[gw * 32 + lane];            // self term: agg + h
    for (int i = beg; i < end; i++) {
        int   s = __ldg(&g_srcA[i]);
        float w = __ldg(&g_wA[i]);
        float2 v = h2[s * 32 + lane];
        acc.x = fmaf(w, v.x, acc.x);
        acc.y = fmaf(w, v.y, acc.y);
    }
    ((float2*)g_bufA)[gw * 32 + lane] = acc;
}

// ---------------- 64x64 GEMM, fused BN-stats / fused input BN+ReLU ---------
// STATS: accumulate per-feature sum & sumsq of Y into g_sum/g_sq
// TRANS: x -> relu(x*g_scale + g_shift) before the GEMM
// SRC/DST: 0 = use pointer arg, 1 = g_bufA, 2 = g_bufB
template <int STATS, int TRANS, int SRC, int DST>
__global__ void __launch_bounds__(128) k_gemm(
    const float* __restrict__ Xarg, const float* __restrict__ W,
    const float* __restrict__ bias, float* __restrict__ Yarg, int n)
{
    const float* X = (SRC == 1) ? g_bufA : (SRC == 2) ? g_bufB : Xarg;
    float*       Y = (DST == 1) ? g_bufA : (DST == 2) ? g_bufB : Yarg;

    __shared__ float4 Ws[64 * 16];      // 16 KB
    __shared__ float  Xs[128 * 33];     // 16.9 KB (one K-half, padded rows)
    __shared__ float  Bs[64];
    __shared__ float  Ss[64];
    __shared__ float  Hs[64];
    __shared__ float  Rs[4 * 128];      // 2 KB

    int tid  = threadIdx.x;
    int base = blockIdx.x * 128;

    for (int i = tid; i < 64 * 16; i += 128) Ws[i] = ((const float4*)W)[i];
    if (tid < 64) {
        Bs[tid] = bias[tid];
        if (TRANS) { Ss[tid] = g_scale[tid]; Hs[tid] = g_shift[tid]; }
    }

    float4 acc[16];
    #pragma unroll
    for (int j = 0; j < 16; j++) acc[j] = make_float4(0.f, 0.f, 0.f, 0.f);

    #pragma unroll
    for (int half = 0; half < 2; half++) {
        __syncthreads();   // previous compute done (and Ws/Bs visible on first pass)
        // stage 128 rows x 32 k-values, coalesced; padded rows (33) -> conflict-free
        for (int i = tid; i < 128 * 8; i += 128) {
            int row = i >> 3, c4 = i & 7;
            float4 v = make_float4(0.f, 0.f, 0.f, 0.f);
            if (base + row < n) v = ((const float4*)X)[(base + row) * 16 + half * 8 + c4];
            float* p = &Xs[row * 33 + c4 * 4];
            p[0] = v.x; p[1] = v.y; p[2] = v.z; p[3] = v.w;
        }
        __syncthreads();

        const float* xr = &Xs[tid * 33];
        #pragma unroll 4
        for (int k = 0; k < 32; k++) {
            float xk = xr[k];
            int   kk = half * 32 + k;
            if (TRANS) xk = fmaxf(fmaf(xk, Ss[kk], Hs[kk]), 0.f);
            #pragma unroll
            for (int j = 0; j < 16; j++) {
                float4 w = Ws[kk * 16 + j];
                acc[j].x = fmaf(xk, w.x, acc[j].x);
                acc[j].y = fmaf(xk, w.y, acc[j].y);
                acc[j].z = fmaf(xk, w.z, acc[j].z);
                acc[j].w = fmaf(xk, w.w, acc[j].w);
            }
        }
    }

    bool valid = (base + tid) < n;
    if (valid) {
        #pragma unroll
        for (int j = 0; j < 16; j++) {
            acc[j].x += Bs[j * 4 + 0];
            acc[j].y += Bs[j * 4 + 1];
            acc[j].z += Bs[j * 4 + 2];
            acc[j].w += Bs[j * 4 + 3];
            ((float4*)Y)[(base + tid) * 16 + j] = acc[j];
        }
    } else {
        // CRITICAL for STATS correctness: with TRANS, zero-filled Xs rows map to
        // relu(shift) != 0, so phantom tail rows would pollute the BN statistics.
        #pragma unroll
        for (int j = 0; j < 16; j++) acc[j] = make_float4(0.f, 0.f, 0.f, 0.f);
    }

    if (STATS) {
        int lane = tid & 31, wid = tid >> 5;
        #pragma unroll
        for (int j = 0; j < 16; j++) {
            float vv[4] = { acc[j].x, acc[j].y, acc[j].z, acc[j].w };
            #pragma unroll
            for (int c = 0; c < 4; c++) {
                float s = vv[c];
                float q = s * s;
                #pragma unroll
                for (int o = 16; o > 0; o >>= 1) {
                    s += __shfl_down_sync(0xffffffffu, s, o);
                    q += __shfl_down_sync(0xffffffffu, q, o);
                }
                if (lane == 0) {
                    Rs[wid * 128 + j * 4 + c]      = s;
                    Rs[wid * 128 + 64 + j * 4 + c] = q;
                }
            }
        }
        __syncthreads();
        if (tid < 128) {
            int f = tid & 63, w = tid >> 6;
            float t = Rs[0 * 128 + w * 64 + f] + Rs[1 * 128 + w * 64 + f]
                    + Rs[2 * 128 + w * 64 + f] + Rs[3 * 128 + w * 64 + f];
            atomicAdd(w ? &g_sq[f] : &g_sum[f], t);
        }
    }
}

// ---------------- BN finalize: fold mean/var/gamma/beta into scale/shift ---
__global__ void k_finalize(const float* __restrict__ gamma,
                           const float* __restrict__ beta) {
    int j = threadIdx.x;
    if (j < EMBD) {
        float mean = g_sum[j] * (1.f / NN);
        float var  = g_sq[j] * (1.f / NN) - mean * mean;
        float rs   = rsqrtf(var + BN_EPS);
        float sc   = rs * gamma[j];
        g_scale[j] = sc;
        g_shift[j] = beta[j] - mean * sc;
        g_sum[j] = 0.f; g_sq[j] = 0.f;
    }
}

// ---------------- outer BN apply + ReLU + residual (t2 = g_bufA) -----------
__global__ void k_resid(float* __restrict__ h) {
    int i = blockIdx.x * blockDim.x + threadIdx.x;
    if (i < NN * EMBD / 4) {
        int fb = (i & 15) * 4;
        float4 v  = ((const float4*)g_bufA)[i];
        float4 hh = ((const float4*)h)[i];
        v.x = fmaxf(fmaf(v.x, g_scale[fb + 0], g_shift[fb + 0]), 0.f) + hh.x;
        v.y = fmaxf(fmaf(v.y, g_scale[fb + 1], g_shift[fb + 1]), 0.f) + hh.y;
        v.z = fmaxf(fmaf(v.z, g_scale[fb + 2], g_shift[fb + 2]), 0.f) + hh.z;
        v.w = fmaxf(fmaf(v.w, g_scale[fb + 3], g_shift[fb + 3]), 0.f) + hh.w;
        ((float4*)h)[i] = v;
    }
}

// ---------------- launch ----------------------------------------------------
extern "C" void kernel_launch(void* const* d_in, const int* in_sizes, int n_in,
                              void* d_out, int out_size) {
    const float* x   = (const float*)d_in[0];
    const int*   ei  = (const int*)d_in[1];
    const float* ew  = (const float*)d_in[3];
    const float* aew = (const float*)d_in[4];
    const float* aeb = (const float*)d_in[5];
    const float* W1  = (const float*)d_in[6];
    const float* b1  = (const float*)d_in[7];
    const float* g1  = (const float*)d_in[8];
    const float* be1 = (const float*)d_in[9];
    const float* W2  = (const float*)d_in[10];
    const float* b2  = (const float*)d_in[11];
    const float* go  = (const float*)d_in[12];
    const float* beo = (const float*)d_in[13];
    float* h = (float*)d_out;

    k_init<<<(NN + 255) / 256, 256>>>();
    k_hist<<<(EE + 255) / 256, 256>>>(ei);
    k_scan<<<1, 1024>>>();
    k_fill<<<(EE + 255) / 256, 256>>>(ei, ew);

    // atom encoder: h = x @ ae_w + ae_b
    k_gemm<0, 0, 0, 0><<<(NN + 127) / 128, 128>>>(x, aew, aeb, h, NN);

    for (int l = 0; l < LL; l++) {
        k_agg<<<(NN * 32 + 255) / 256, 256>>>(h);                    // -> bufA
        k_gemm<1, 0, 1, 2><<<(NN + 127) / 128, 128>>>(               // bufA -> bufB
            nullptr, W1 + l * EMBD * EMBD, b1 + l * EMBD, nullptr, NN);
        k_finalize<<<1, 64>>>(g1 + l * EMBD, be1 + l * EMBD);
        k_gemm<1, 1, 2, 1><<<(NN + 127) / 128, 128>>>(               // bufB -> bufA
            nullptr, W2 + l * EMBD * EMBD, b2 + l * EMBD, nullptr, NN);
        k_finalize<<<1, 64>>>(go + l * EMBD, beo + l * EMBD);
        k_resid<<<(NN * EMBD / 4 + 255) / 256, 256>>>(h);
    }
}

// round 4
// speedup vs baseline: 1.1011x; 1.1011x over previous
#include <cuda_runtime.h>

#define NN 50000
#define EE 800000
#define EMBD 64
#define LL 4
#define BN_EPS 1e-5f
#define GROUP 512
#define NG ((NN + GROUP - 1) / GROUP)   // 98

// ---------------- scratch (device globals; no allocation allowed) ----------
__device__ __align__(256) float g_bufA[NN * EMBD];   // agg output / t2
__device__ __align__(256) float g_bufB[NN * EMBD];   // t (gemm1 out)
__device__ int   g_off[NN + 1];
__device__ int   g_cur[NN];
__device__ int2  g_edge[EE];            // packed (src, weight-bits)
__device__ int   g_part[NG];
__device__ float g_sumL[8][64];         // per-BN stat slots (4 layers x {inner,outer})
__device__ float g_sqL[8][64];

// ---------------- init: zero counters + all stat slots ---------------------
__global__ void k_init() {
    int i = blockIdx.x * blockDim.x + threadIdx.x;
    if (i < NN) g_cur[i] = 0;
    if (i < 8 * 64) { (&g_sumL[0][0])[i] = 0.f; (&g_sqL[0][0])[i] = 0.f; }
}

__global__ void k_hist(const int* __restrict__ ei) {
    int e = blockIdx.x * blockDim.x + threadIdx.x;
    if (e < EE) atomicAdd(&g_cur[ei[EE + e]], 1);
}

// ---------------- 3-phase exclusive scan over g_cur -> g_off ---------------
__global__ void k_scanA() {
    __shared__ int s_warp[32];
    int tid = threadIdx.x, lane = tid & 31, wid = tid >> 5;
    int i = blockIdx.x * GROUP + tid;
    int d = (i < NN) ? g_cur[i] : 0;
    int v = d;
    #pragma unroll
    for (int o = 1; o < 32; o <<= 1) {
        int t = __shfl_up_sync(0xffffffffu, v, o);
        if (lane >= o) v += t;
    }
    if (lane == 31) s_warp[wid] = v;
    __syncthreads();
    if (wid == 0) {
        int w = (lane < 16) ? s_warp[lane] : 0;
        #pragma unroll
        for (int o = 1; o < 32; o <<= 1) {
            int t = __shfl_up_sync(0xffffffffu, w, o);
            if (lane >= o) w += t;
        }
        if (lane < 16) s_warp[lane] = w;
    }
    __syncthreads();
    int excl = (wid ? s_warp[wid - 1] : 0) + v - d;
    if (i < NN) g_off[i] = excl;
    if (tid == 0) g_part[blockIdx.x] = s_warp[15];   // block total
}

__global__ void k_scanB() {
    __shared__ int s[NG];
    int tid = threadIdx.x;
    if (tid < NG) s[tid] = g_part[tid];
    __syncthreads();
    if (tid == 0) {
        int run = 0;
        for (int j = 0; j < NG; j++) { int t = s[j]; s[j] = run; run += t; }
    }
    __syncthreads();
    if (tid < NG) g_part[tid] = s[tid];
}

__global__ void k_scanC() {
    int i = blockIdx.x * GROUP + threadIdx.x;
    if (i < NN) {
        int o = g_off[i] + g_part[blockIdx.x];
        g_off[i] = o;
        g_cur[i] = o;
    }
    if (i == 0) g_off[NN] = EE;
}

__global__ void k_fill(const int* __restrict__ ei, const float* __restrict__ ew) {
    int e = blockIdx.x * blockDim.x + threadIdx.x;
    if (e < EE) {
        int d = ei[EE + e];
        int p = atomicAdd(&g_cur[d], 1);
        g_edge[p] = make_int2(ei[e], __float_as_int(ew[e]));
    }
}

// ---------------- aggregation: warp per node, no atomics -------------------
// out = g_bufA ; acc starts with self term (agg + h)
__global__ void k_agg(const float* __restrict__ h) {
    int gw   = (blockIdx.x * blockDim.x + threadIdx.x) >> 5;
    int lane = threadIdx.x & 31;
    if (gw >= NN) return;
    int beg = g_off[gw], end = g_off[gw + 1];
    const float2* h2 = (const float2*)h;
    float2 acc = h2[gw * 32 + lane];
    int i = beg;
    for (; i + 2 <= end; i += 2) {
        int2 e0 = __ldg(&g_edge[i]);
        int2 e1 = __ldg(&g_edge[i + 1]);
        float2 v0 = h2[e0.x * 32 + lane];
        float2 v1 = h2[e1.x * 32 + lane];
        float w0 = __int_as_float(e0.y), w1 = __int_as_float(e1.y);
        acc.x = fmaf(w0, v0.x, acc.x);
        acc.y = fmaf(w0, v0.y, acc.y);
        acc.x = fmaf(w1, v1.x, acc.x);
        acc.y = fmaf(w1, v1.y, acc.y);
    }
    if (i < end) {
        int2 e0 = __ldg(&g_edge[i]);
        float2 v0 = h2[e0.x * 32 + lane];
        float w0 = __int_as_float(e0.y);
        acc.x = fmaf(w0, v0.x, acc.x);
        acc.y = fmaf(w0, v0.y, acc.y);
    }
    ((float2*)g_bufA)[gw * 32 + lane] = acc;
}

// ---------------- 64x64 GEMM, fused BN-stats in / out ----------------------
// STATS: accumulate per-feature sum & sumsq of Y into slotOut
// TRANS: x -> relu(x*scale + shift), scale/shift computed from slotIn + gamma/beta
// SRC/DST: 0 = use pointer arg, 1 = g_bufA, 2 = g_bufB
template <int STATS, int TRANS, int SRC, int DST>
__global__ void __launch_bounds__(128) k_gemm(
    const float* __restrict__ Xarg, const float* __restrict__ W,
    const float* __restrict__ bias, float* __restrict__ Yarg,
    const float* __restrict__ gma, const float* __restrict__ bta,
    int slotIn, int slotOut, int n)
{
    const float* X = (SRC == 1) ? g_bufA : (SRC == 2) ? g_bufB : Xarg;
    float*       Y = (DST == 1) ? g_bufA : (DST == 2) ? g_bufB : Yarg;

    __shared__ float4 Ws[64 * 16];      // 16 KB
    __shared__ float  Xs[128 * 33];     // 16.9 KB (one K-half, padded rows)
    __shared__ float  Bs[64];
    __shared__ float  Ss[64];
    __shared__ float  Hs[64];
    __shared__ float  Rs[4 * 128];      // 2 KB

    int tid  = threadIdx.x;
    int base = blockIdx.x * 128;

    for (int i = tid; i < 64 * 16; i += 128) Ws[i] = ((const float4*)W)[i];
    if (tid < 64) {
        Bs[tid] = bias[tid];
        if (TRANS) {
            // fold BN (batch stats) + gamma/beta into scale/shift, inline
            float mean = g_sumL[slotIn][tid] * (1.f / NN);
            float var  = g_sqL[slotIn][tid] * (1.f / NN) - mean * mean;
            float rs   = rsqrtf(var + BN_EPS);
            float sc   = rs * gma[tid];
            Ss[tid] = sc;
            Hs[tid] = bta[tid] - mean * sc;
        }
    }

    float4 acc[16];
    #pragma unroll
    for (int j = 0; j < 16; j++) acc[j] = make_float4(0.f, 0.f, 0.f, 0.f);

    #pragma unroll
    for (int half = 0; half < 2; half++) {
        __syncthreads();   // previous compute done (and Ws/Bs/Ss/Hs visible first pass)
        for (int i = tid; i < 128 * 8; i += 128) {
            int row = i >> 3, c4 = i & 7;
            float4 v = make_float4(0.f, 0.f, 0.f, 0.f);
            if (base + row < n) v = ((const float4*)X)[(base + row) * 16 + half * 8 + c4];
            float* p = &Xs[row * 33 + c4 * 4];
            p[0] = v.x; p[1] = v.y; p[2] = v.z; p[3] = v.w;
        }
        __syncthreads();

        const float* xr = &Xs[tid * 33];
        #pragma unroll 4
        for (int k = 0; k < 32; k++) {
            float xk = xr[k];
            int   kk = half * 32 + k;
            if (TRANS) xk = fmaxf(fmaf(xk, Ss[kk], Hs[kk]), 0.f);
            #pragma unroll
            for (int j = 0; j < 16; j++) {
                float4 w = Ws[kk * 16 + j];
                acc[j].x = fmaf(xk, w.x, acc[j].x);
                acc[j].y = fmaf(xk, w.y, acc[j].y);
                acc[j].z = fmaf(xk, w.z, acc[j].z);
                acc[j].w = fmaf(xk, w.w, acc[j].w);
            }
        }
    }

    bool valid = (base + tid) < n;
    if (valid) {
        #pragma unroll
        for (int j = 0; j < 16; j++) {
            acc[j].x += Bs[j * 4 + 0];
            acc[j].y += Bs[j * 4 + 1];
            acc[j].z += Bs[j * 4 + 2];
            acc[j].w += Bs[j * 4 + 3];
            ((float4*)Y)[(base + tid) * 16 + j] = acc[j];
        }
    } else {
        // phantom tail rows must contribute zeros to BN stats (TRANS maps 0 -> relu(shift) != 0)
        #pragma unroll
        for (int j = 0; j < 16; j++) acc[j] = make_float4(0.f, 0.f, 0.f, 0.f);
    }

    if (STATS) {
        int lane = tid & 31, wid = tid >> 5;
        #pragma unroll
        for (int j = 0; j < 16; j++) {
            float vv[4] = { acc[j].x, acc[j].y, acc[j].z, acc[j].w };
            #pragma unroll
            for (int c = 0; c < 4; c++) {
                float s = vv[c];
                float q = s * s;
                #pragma unroll
                for (int o = 16; o > 0; o >>= 1) {
                    s += __shfl_down_sync(0xffffffffu, s, o);
                    q += __shfl_down_sync(0xffffffffu, q, o);
                }
                if (lane == 0) {
                    Rs[wid * 128 + j * 4 + c]      = s;
                    Rs[wid * 128 + 64 + j * 4 + c] = q;
                }
            }
        }
        __syncthreads();
        if (tid < 128) {
            int f = tid & 63, w = tid >> 6;
            float t = Rs[0 * 128 + w * 64 + f] + Rs[1 * 128 + w * 64 + f]
                    + Rs[2 * 128 + w * 64 + f] + Rs[3 * 128 + w * 64 + f];
            atomicAdd(w ? &g_sqL[slotOut][f] : &g_sumL[slotOut][f], t);
        }
    }
}

// ---------------- outer BN apply + ReLU + residual (t2 = g_bufA) -----------
__global__ void __launch_bounds__(256) k_resid(
    float* __restrict__ h, const float* __restrict__ gma,
    const float* __restrict__ bta, int slot)
{
    __shared__ float Ss[64];
    __shared__ float Hs[64];
    int tid = threadIdx.x;
    if (tid < 64) {
        float mean = g_sumL[slot][tid] * (1.f / NN);
        float var  = g_sqL[slot][tid] * (1.f / NN) - mean * mean;
        float rs   = rsqrtf(var + BN_EPS);
        float sc   = rs * gma[tid];
        Ss[tid] = sc;
        Hs[tid] = bta[tid] - mean * sc;
    }
    __syncthreads();
    int i = blockIdx.x * blockDim.x + tid;
    if (i < NN * EMBD / 4) {
        int fb = (i & 15) * 4;
        float4 v  = ((const float4*)g_bufA)[i];
        float4 hh = ((const float4*)h)[i];
        v.x = fmaxf(fmaf(v.x, Ss[fb + 0], Hs[fb + 0]), 0.f) + hh.x;
        v.y = fmaxf(fmaf(v.y, Ss[fb + 1], Hs[fb + 1]), 0.f) + hh.y;
        v.z = fmaxf(fmaf(v.z, Ss[fb + 2], Hs[fb + 2]), 0.f) + hh.z;
        v.w = fmaxf(fmaf(v.w, Ss[fb + 3], Hs[fb + 3]), 0.f) + hh.w;
        ((float4*)h)[i] = v;
    }
}

// ---------------- launch ----------------------------------------------------
extern "C" void kernel_launch(void* const* d_in, const int* in_sizes, int n_in,
                              void* d_out, int out_size) {
    const float* x   = (const float*)d_in[0];
    const int*   ei  = (const int*)d_in[1];
    const float* ew  = (const float*)d_in[3];
    const float* aew = (const float*)d_in[4];
    const float* aeb = (const float*)d_in[5];
    const float* W1  = (const float*)d_in[6];
    const float* b1  = (const float*)d_in[7];
    const float* g1  = (const float*)d_in[8];
    const float* be1 = (const float*)d_in[9];
    const float* W2  = (const float*)d_in[10];
    const float* b2  = (const float*)d_in[11];
    const float* go  = (const float*)d_in[12];
    const float* beo = (const float*)d_in[13];
    float* h = (float*)d_out;

    k_init<<<(NN + 255) / 256, 256>>>();
    k_hist<<<(EE + 255) / 256, 256>>>(ei);
    k_scanA<<<NG, GROUP>>>();
    k_scanB<<<1, 128>>>();
    k_scanC<<<NG, GROUP>>>();
    k_fill<<<(EE + 255) / 256, 256>>>(ei, ew);

    // atom encoder: h = x @ ae_w + ae_b
    k_gemm<0, 0, 0, 0><<<(NN + 127) / 128, 128>>>(
        x, aew, aeb, h, nullptr, nullptr, 0, 0, NN);

    for (int l = 0; l < LL; l++) {
        int sIn = 2 * l, sOut = 2 * l + 1;
        k_agg<<<(NN * 32 + 255) / 256, 256>>>(h);                    // -> bufA
        k_gemm<1, 0, 1, 2><<<(NN + 127) / 128, 128>>>(               // bufA -> bufB, stats->sIn
            nullptr, W1 + l * EMBD * EMBD, b1 + l * EMBD, nullptr,
            nullptr, nullptr, 0, sIn, NN);
        k_gemm<1, 1, 2, 1><<<(NN + 127) / 128, 128>>>(               // bufB -> bufA, BN(sIn), stats->sOut
            nullptr, W2 + l * EMBD * EMBD, b2 + l * EMBD, nullptr,
            g1 + l * EMBD, be1 + l * EMBD, sIn, sOut, NN);
        k_resid<<<(NN * EMBD / 4 + 255) / 256, 256>>>(               // h += relu(BN(bufA))
            h, go + l * EMBD, beo + l * EMBD, sOut);
    }
}

// round 5
// speedup vs baseline: 1.1186x; 1.0159x over previous
#include <cuda_runtime.h>

#define NN 50000
#define EE 800000
#define EMBD 64
#define LL 4
#define BN_EPS 1e-5f
#define GROUP 512
#define NG ((NN + GROUP - 1) / GROUP)   // 98

// ---------------- scratch (device globals; no allocation allowed) ----------
__device__ __align__(256) float g_bufA[NN * EMBD];   // agg output / t2
__device__ __align__(256) float g_bufB[NN * EMBD];   // t (gemm1 out)
__device__ int   g_off[NN + 1];
__device__ int   g_cur[NN];
__device__ int2  g_edge[EE];            // packed (src, weight-bits)
__device__ int   g_part[NG];
__device__ float g_sumL[8][64];         // per-BN stat slots (4 layers x {inner,outer})
__device__ float g_sqL[8][64];

// ---------------- init: zero counters + all stat slots ---------------------
__global__ void k_init() {
    int i = blockIdx.x * blockDim.x + threadIdx.x;
    if (i < NN) g_cur[i] = 0;
    if (i < 8 * 64) { (&g_sumL[0][0])[i] = 0.f; (&g_sqL[0][0])[i] = 0.f; }
}

__global__ void k_hist(const int* __restrict__ ei) {
    int e = blockIdx.x * blockDim.x + threadIdx.x;
    if (e < EE) atomicAdd(&g_cur[ei[EE + e]], 1);
}

// ---------------- 3-phase exclusive scan over g_cur -> g_off ---------------
__global__ void k_scanA() {
    __shared__ int s_warp[32];
    int tid = threadIdx.x, lane = tid & 31, wid = tid >> 5;
    int i = blockIdx.x * GROUP + tid;
    int d = (i < NN) ? g_cur[i] : 0;
    int v = d;
    #pragma unroll
    for (int o = 1; o < 32; o <<= 1) {
        int t = __shfl_up_sync(0xffffffffu, v, o);
        if (lane >= o) v += t;
    }
    if (lane == 31) s_warp[wid] = v;
    __syncthreads();
    if (wid == 0) {
        int w = (lane < 16) ? s_warp[lane] : 0;
        #pragma unroll
        for (int o = 1; o < 32; o <<= 1) {
            int t = __shfl_up_sync(0xffffffffu, w, o);
            if (lane >= o) w += t;
        }
        if (lane < 16) s_warp[lane] = w;
    }
    __syncthreads();
    int excl = (wid ? s_warp[wid - 1] : 0) + v - d;
    if (i < NN) g_off[i] = excl;
    if (tid == 0) g_part[blockIdx.x] = s_warp[15];   // block total
}

// parallel scan over NG (=98) partials, one 128-thread block
__global__ void k_scanB() {
    __shared__ int wtot[4];
    int tid = threadIdx.x, lane = tid & 31, wid = tid >> 5;
    int d = (tid < NG) ? g_part[tid] : 0;
    int v = d;
    #pragma unroll
    for (int o = 1; o < 32; o <<= 1) {
        int t = __shfl_up_sync(0xffffffffu, v, o);
        if (lane >= o) v += t;
    }
    if (lane == 31) wtot[wid] = v;
    __syncthreads();
    int add = 0;
    #pragma unroll
    for (int w = 0; w < 4; w++) add += (w < wid) ? wtot[w] : 0;
    if (tid < NG) g_part[tid] = add + v - d;
}

__global__ void k_scanC() {
    int i = blockIdx.x * GROUP + threadIdx.x;
    if (i < NN) {
        int o = g_off[i] + g_part[blockIdx.x];
        g_off[i] = o;
        g_cur[i] = o;
    }
    if (i == 0) g_off[NN] = EE;
}

__global__ void k_fill(const int* __restrict__ ei, const float* __restrict__ ew) {
    int e = blockIdx.x * blockDim.x + threadIdx.x;
    if (e < EE) {
        int d = ei[EE + e];
        int p = atomicAdd(&g_cur[d], 1);
        g_edge[p] = make_int2(ei[e], __float_as_int(ew[e]));
    }
}

// ---------------- aggregation: warp per node, no atomics -------------------
__global__ void k_agg(const float* __restrict__ h) {
    int gw   = (blockIdx.x * blockDim.x + threadIdx.x) >> 5;
    int lane = threadIdx.x & 31;
    if (gw >= NN) return;
    int beg = g_off[gw], end = g_off[gw + 1];
    const float2* h2 = (const float2*)h;
    float2 acc = h2[gw * 32 + lane];            // self term: agg + h
    int i = beg;
    for (; i + 2 <= end; i += 2) {
        int2 e0 = __ldg(&g_edge[i]);
        int2 e1 = __ldg(&g_edge[i + 1]);
        float2 v0 = h2[e0.x * 32 + lane];
        float2 v1 = h2[e1.x * 32 + lane];
        float w0 = __int_as_float(e0.y), w1 = __int_as_float(e1.y);
        acc.x = fmaf(w0, v0.x, acc.x);
        acc.y = fmaf(w0, v0.y, acc.y);
        acc.x = fmaf(w1, v1.x, acc.x);
        acc.y = fmaf(w1, v1.y, acc.y);
    }
    if (i < end) {
        int2 e0 = __ldg(&g_edge[i]);
        float2 v0 = h2[e0.x * 32 + lane];
        float w0 = __int_as_float(e0.y);
        acc.x = fmaf(w0, v0.x, acc.x);
        acc.y = fmaf(w0, v0.y, acc.y);
    }
    ((float2*)g_bufA)[gw * 32 + lane] = acc;
}

// ---------------- 64x64 GEMM via packed f32x2 (FFMA2) ----------------------
// STATS: accumulate per-feature sum & sumsq of Y into slotOut
// TRANS: x -> relu(x*scale + shift), scale/shift from slotIn stats + gamma/beta
// SRC/DST: 0 = use pointer arg, 1 = g_bufA, 2 = g_bufB
template <int STATS, int TRANS, int SRC, int DST>
__global__ void __launch_bounds__(128) k_gemm(
    const float* __restrict__ Xarg, const float* __restrict__ W,
    const float* __restrict__ bias, float* __restrict__ Yarg,
    const float* __restrict__ gma, const float* __restrict__ bta,
    int slotIn, int slotOut, int n)
{
    const float* X = (SRC == 1) ? g_bufA : (SRC == 2) ? g_bufB : Xarg;
    float*       Y = (DST == 1) ? g_bufA : (DST == 2) ? g_bufB : Yarg;

    __shared__ float4 Ws[64 * 16];      // 16 KB, row k: 64 output features
    __shared__ float  Xs[128 * 33];     // 16.9 KB (one K-half, padded rows)
    __shared__ float  Bs[64];
    __shared__ float  Ss[64];
    __shared__ float  Hs[64];
    __shared__ float  Rs[4 * 128];      // 2 KB

    int tid  = threadIdx.x;
    int base = blockIdx.x * 128;

    for (int i = tid; i < 64 * 16; i += 128) Ws[i] = ((const float4*)W)[i];
    if (tid < 64) {
        Bs[tid] = bias[tid];
        if (TRANS) {
            float mean = g_sumL[slotIn][tid] * (1.f / NN);
            float var  = g_sqL[slotIn][tid] * (1.f / NN) - mean * mean;
            float rs   = rsqrtf(var + BN_EPS);
            float sc   = rs * gma[tid];
            Ss[tid] = sc;
            Hs[tid] = bta[tid] - mean * sc;
        }
    }

    // 32 packed f32x2 accumulators = 64 fp32 outputs
    unsigned long long acc2[32];
    #pragma unroll
    for (int j = 0; j < 32; j++) acc2[j] = 0ull;

    #pragma unroll
    for (int half = 0; half < 2; half++) {
        __syncthreads();   // previous compute done (and Ws/Bs/Ss/Hs visible first pass)
        for (int i = tid; i < 128 * 8; i += 128) {
            int row = i >> 3, c4 = i & 7;
            float4 v = make_float4(0.f, 0.f, 0.f, 0.f);
            if (base + row < n) v = ((const float4*)X)[(base + row) * 16 + half * 8 + c4];
            float* p = &Xs[row * 33 + c4 * 4];
            p[0] = v.x; p[1] = v.y; p[2] = v.z; p[3] = v.w;
        }
        __syncthreads();

        const float* xr = &Xs[tid * 33];
        #pragma unroll 4
        for (int k = 0; k < 32; k++) {
            float xk = xr[k];
            int   kk = half * 32 + k;
            if (TRANS) xk = fmaxf(fmaf(xk, Ss[kk], Hs[kk]), 0.f);
            unsigned long long xk2;
            unsigned int xi = __float_as_uint(xk);
            asm("mov.b64 %0, {%1, %1};" : "=l"(xk2) : "r"(xi));
            const ulonglong2* wrow = (const ulonglong2*)&Ws[kk * 16];
            #pragma unroll
            for (int j = 0; j < 16; j++) {
                ulonglong2 w2 = wrow[j];        // one LDS.128 (broadcast)
                asm("fma.rn.f32x2 %0, %1, %2, %0;" : "+l"(acc2[2 * j])     : "l"(xk2), "l"(w2.x));
                asm("fma.rn.f32x2 %0, %1, %2, %0;" : "+l"(acc2[2 * j + 1]) : "l"(xk2), "l"(w2.y));
            }
        }
    }

    // unpack to float4 lanes
    float4 acc[16];
    #pragma unroll
    for (int j = 0; j < 16; j++) {
        uint2 lo = *(uint2*)&acc2[2 * j];
        uint2 hi = *(uint2*)&acc2[2 * j + 1];
        acc[j].x = __uint_as_float(lo.x);
        acc[j].y = __uint_as_float(lo.y);
        acc[j].z = __uint_as_float(hi.x);
        acc[j].w = __uint_as_float(hi.y);
    }

    bool valid = (base + tid) < n;
    if (valid) {
        #pragma unroll
        for (int j = 0; j < 16; j++) {
            acc[j].x += Bs[j * 4 + 0];
            acc[j].y += Bs[j * 4 + 1];
            acc[j].z += Bs[j * 4 + 2];
            acc[j].w += Bs[j * 4 + 3];
            ((float4*)Y)[(base + tid) * 16 + j] = acc[j];
        }
    } else {
        // phantom tail rows must contribute zeros to BN stats
        #pragma unroll
        for (int j = 0; j < 16; j++) acc[j] = make_float4(0.f, 0.f, 0.f, 0.f);
    }

    if (STATS) {
        int lane = tid & 31, wid = tid >> 5;
        #pragma unroll
        for (int j = 0; j < 16; j++) {
            float vv[4] = { acc[j].x, acc[j].y, acc[j].z, acc[j].w };
            #pragma unroll
            for (int c = 0; c < 4; c++) {
                float s = vv[c];
                float q = s * s;
                #pragma unroll
                for (int o = 16; o > 0; o >>= 1) {
                    s += __shfl_down_sync(0xffffffffu, s, o);
                    q += __shfl_down_sync(0xffffffffu, q, o);
                }
                if (lane == 0) {
                    Rs[wid * 128 + j * 4 + c]      = s;
                    Rs[wid * 128 + 64 + j * 4 + c] = q;
                }
            }
        }
        __syncthreads();
        if (tid < 128) {
            int f = tid & 63, w = tid >> 6;
            float t = Rs[0 * 128 + w * 64 + f] + Rs[1 * 128 + w * 64 + f]
                    + Rs[2 * 128 + w * 64 + f] + Rs[3 * 128 + w * 64 + f];
            atomicAdd(w ? &g_sqL[slotOut][f] : &g_sumL[slotOut][f], t);
        }
    }
}

// ---------------- outer BN apply + ReLU + residual (t2 = g_bufA) -----------
__global__ void __launch_bounds__(256) k_resid(
    float* __restrict__ h, const float* __restrict__ gma,
    const float* __restrict__ bta, int slot)
{
    __shared__ float Ss[64];
    __shared__ float Hs[64];
    int tid = threadIdx.x;
    if (tid < 64) {
        float mean = g_sumL[slot][tid] * (1.f / NN);
        float var  = g_sqL[slot][tid] * (1.f / NN) - mean * mean;
        float rs   = rsqrtf(var + BN_EPS);
        float sc   = rs * gma[tid];
        Ss[tid] = sc;
        Hs[tid] = bta[tid] - mean * sc;
    }
    __syncthreads();
    int i = blockIdx.x * blockDim.x + tid;
    if (i < NN * EMBD / 4) {
        int fb = (i & 15) * 4;
        float4 v  = ((const float4*)g_bufA)[i];
        float4 hh = ((const float4*)h)[i];
        v.x = fmaxf(fmaf(v.x, Ss[fb + 0], Hs[fb + 0]), 0.f) + hh.x;
        v.y = fmaxf(fmaf(v.y, Ss[fb + 1], Hs[fb + 1]), 0.f) + hh.y;
        v.z = fmaxf(fmaf(v.z, Ss[fb + 2], Hs[fb + 2]), 0.f) + hh.z;
        v.w = fmaxf(fmaf(v.w, Ss[fb + 3], Hs[fb + 3]), 0.f) + hh.w;
        ((float4*)h)[i] = v;
    }
}

// ---------------- launch ----------------------------------------------------
extern "C" void kernel_launch(void* const* d_in, const int* in_sizes, int n_in,
                              void* d_out, int out_size) {
    const float* x   = (const float*)d_in[0];
    const int*   ei  = (const int*)d_in[1];
    const float* ew  = (const float*)d_in[3];
    const float* aew = (const float*)d_in[4];
    const float* aeb = (const float*)d_in[5];
    const float* W1  = (const float*)d_in[6];
    const float* b1  = (const float*)d_in[7];
    const float* g1  = (const float*)d_in[8];
    const float* be1 = (const float*)d_in[9];
    const float* W2  = (const float*)d_in[10];
    const float* b2  = (const float*)d_in[11];
    const float* go  = (const float*)d_in[12];
    const float* beo = (const float*)d_in[13];
    float* h = (float*)d_out;

    k_init<<<(NN + 255) / 256, 256>>>();
    k_hist<<<(EE + 255) / 256, 256>>>(ei);
    k_scanA<<<NG, GROUP>>>();
    k_scanB<<<1, 128>>>();
    k_scanC<<<NG, GROUP>>>();
    k_fill<<<(EE + 255) / 256, 256>>>(ei, ew);

    // atom encoder: h = x @ ae_w + ae_b
    k_gemm<0, 0, 0, 0><<<(NN + 127) / 128, 128>>>(
        x, aew, aeb, h, nullptr, nullptr, 0, 0, NN);

    for (int l = 0; l < LL; l++) {
        int sIn = 2 * l, sOut = 2 * l + 1;
        k_agg<<<(NN * 32 + 255) / 256, 256>>>(h);                    // -> bufA
        k_gemm<1, 0, 1, 2><<<(NN + 127) / 128, 128>>>(               // bufA -> bufB, stats->sIn
            nullptr, W1 + l * EMBD * EMBD, b1 + l * EMBD, nullptr,
            nullptr, nullptr, 0, sIn, NN);
        k_gemm<1, 1, 2, 1><<<(NN + 127) / 128, 128>>>(               // bufB -> bufA, BN(sIn), stats->sOut
            nullptr, W2 + l * EMBD * EMBD, b2 + l * EMBD, nullptr,
            g1 + l * EMBD, be1 + l * EMBD, sIn, sOut, NN);
        k_resid<<<(NN * EMBD / 4 + 255) / 256, 256>>>(               // h += relu(BN(bufA))
            h, go + l * EMBD, beo + l * EMBD, sOut);
    }
}